// round 1
// baseline (speedup 1.0000x reference)
#include <cuda_runtime.h>
#include <math.h>

#define T_TOK 16384   // B*S
#define DIMN  1024
#define BANKN 8192

// ---- scratch (allocation-free: device globals) ----
__device__ float g_Q [(size_t)T_TOK * DIMN];   // 64 MB
__device__ float g_K [(size_t)BANKN * DIMN];   // 32 MB
__device__ float g_VT[(size_t)DIMN * BANKN];   // 32 MB (values, transposed: [d][n])
__device__ float g_S [(size_t)T_TOK * BANKN];  // 512 MB (scores -> attn)
__device__ float g_R [(size_t)T_TOK * DIMN];   // 64 MB (retrieved)
__device__ float g_H [(size_t)T_TOK * DIMN];   // 64 MB (pre-LN)

// ============================================================
// Generic NT GEMM: C[M,N] = alpha * A[M,K] * W[N,K]^T (+ bias[N])
// BM=BN=128, BK=8, 256 threads, 8x8 micro-tile per thread.
// transC=1 stores C[col*M + row] (used to produce VT).
// ============================================================
__global__ __launch_bounds__(256) void gemm_nt_kernel(
    const float* __restrict__ A, const float* __restrict__ W,
    const float* __restrict__ bias, float* __restrict__ C,
    int M, int N, int K, float alpha, int transC)
{
    __shared__ float As[8][128];
    __shared__ float Bs[8][128];
    const int tid = threadIdx.x;
    const int tx = tid & 15;        // 16 col-threads
    const int ty = tid >> 4;        // 16 row-threads
    const int bx = blockIdx.x;      // N tile
    const int by = blockIdx.y;      // M tile

    const float* Ab = A + (size_t)by * 128 * K;
    const float* Wb = W + (size_t)bx * 128 * K;
    const int lrow = tid >> 1;          // 0..127
    const int lcol = (tid & 1) * 4;     // 0 or 4

    float acc[8][8];
#pragma unroll
    for (int i = 0; i < 8; i++)
#pragma unroll
        for (int j = 0; j < 8; j++) acc[i][j] = 0.f;

    for (int k0 = 0; k0 < K; k0 += 8) {
        float4 av = *(const float4*)(Ab + (size_t)lrow * K + (k0 + lcol));
        float4 wv = *(const float4*)(Wb + (size_t)lrow * K + (k0 + lcol));
        __syncthreads();
        As[lcol + 0][lrow] = av.x; As[lcol + 1][lrow] = av.y;
        As[lcol + 2][lrow] = av.z; As[lcol + 3][lrow] = av.w;
        Bs[lcol + 0][lrow] = wv.x; Bs[lcol + 1][lrow] = wv.y;
        Bs[lcol + 2][lrow] = wv.z; Bs[lcol + 3][lrow] = wv.w;
        __syncthreads();
#pragma unroll
        for (int kk = 0; kk < 8; kk++) {
            float4 a0 = *(const float4*)&As[kk][ty * 8];
            float4 a1 = *(const float4*)&As[kk][ty * 8 + 4];
            float4 b0 = *(const float4*)&Bs[kk][tx * 8];
            float4 b1 = *(const float4*)&Bs[kk][tx * 8 + 4];
            float af[8] = {a0.x, a0.y, a0.z, a0.w, a1.x, a1.y, a1.z, a1.w};
            float bw[8] = {b0.x, b0.y, b0.z, b0.w, b1.x, b1.y, b1.z, b1.w};
#pragma unroll
            for (int i = 0; i < 8; i++)
#pragma unroll
                for (int j = 0; j < 8; j++)
                    acc[i][j] += af[i] * bw[j];
        }
    }

#pragma unroll
    for (int i = 0; i < 8; i++) {
        int row = by * 128 + ty * 8 + i;
        if (!transC) {
            int col0 = bx * 128 + tx * 8;
            float4 o0, o1;
            float b0 = bias ? bias[col0 + 0] : 0.f;
            float b1 = bias ? bias[col0 + 1] : 0.f;
            float b2 = bias ? bias[col0 + 2] : 0.f;
            float b3 = bias ? bias[col0 + 3] : 0.f;
            float b4 = bias ? bias[col0 + 4] : 0.f;
            float b5 = bias ? bias[col0 + 5] : 0.f;
            float b6 = bias ? bias[col0 + 6] : 0.f;
            float b7 = bias ? bias[col0 + 7] : 0.f;
            o0.x = acc[i][0] * alpha + b0; o0.y = acc[i][1] * alpha + b1;
            o0.z = acc[i][2] * alpha + b2; o0.w = acc[i][3] * alpha + b3;
            o1.x = acc[i][4] * alpha + b4; o1.y = acc[i][5] * alpha + b5;
            o1.z = acc[i][6] * alpha + b6; o1.w = acc[i][7] * alpha + b7;
            *(float4*)(C + (size_t)row * N + col0)     = o0;
            *(float4*)(C + (size_t)row * N + col0 + 4) = o1;
        } else {
#pragma unroll
            for (int j = 0; j < 8; j++) {
                int col = bx * 128 + tx * 8 + j;
                float v = acc[i][j] * alpha + (bias ? bias[col] : 0.f);
                C[(size_t)col * M + row] = v;
            }
        }
    }
}

// ============================================================
// Final GEMM: H[t,d] = sum_k [x|R][t,k] * wf[d,k] + bf[d] + x[t,d]
// M = T_TOK, N = DIMN, K = 2048 (first 1024 from x, rest from R)
// ============================================================
__global__ __launch_bounds__(256) void gemm_final_kernel(
    const float* __restrict__ x, const float* __restrict__ R,
    const float* __restrict__ wf, const float* __restrict__ bf,
    float* __restrict__ H)
{
    __shared__ float As[8][128];
    __shared__ float Bs[8][128];
    const int tid = threadIdx.x;
    const int tx = tid & 15;
    const int ty = tid >> 4;
    const int bx = blockIdx.x;
    const int by = blockIdx.y;
    const int lrow = tid >> 1;
    const int lcol = (tid & 1) * 4;

    const float* Wb = wf + (size_t)bx * 128 * 2048;

    float acc[8][8];
#pragma unroll
    for (int i = 0; i < 8; i++)
#pragma unroll
        for (int j = 0; j < 8; j++) acc[i][j] = 0.f;

    for (int k0 = 0; k0 < 2048; k0 += 8) {
        const float* Ab = (k0 < 1024)
            ? (x + (size_t)by * 128 * 1024 + k0)
            : (R + (size_t)by * 128 * 1024 + (k0 - 1024));
        float4 av = *(const float4*)(Ab + (size_t)lrow * 1024 + lcol);
        float4 wv = *(const float4*)(Wb + (size_t)lrow * 2048 + k0 + lcol);
        __syncthreads();
        As[lcol + 0][lrow] = av.x; As[lcol + 1][lrow] = av.y;
        As[lcol + 2][lrow] = av.z; As[lcol + 3][lrow] = av.w;
        Bs[lcol + 0][lrow] = wv.x; Bs[lcol + 1][lrow] = wv.y;
        Bs[lcol + 2][lrow] = wv.z; Bs[lcol + 3][lrow] = wv.w;
        __syncthreads();
#pragma unroll
        for (int kk = 0; kk < 8; kk++) {
            float4 a0 = *(const float4*)&As[kk][ty * 8];
            float4 a1 = *(const float4*)&As[kk][ty * 8 + 4];
            float4 b0 = *(const float4*)&Bs[kk][tx * 8];
            float4 b1 = *(const float4*)&Bs[kk][tx * 8 + 4];
            float af[8] = {a0.x, a0.y, a0.z, a0.w, a1.x, a1.y, a1.z, a1.w};
            float bw[8] = {b0.x, b0.y, b0.z, b0.w, b1.x, b1.y, b1.z, b1.w};
#pragma unroll
            for (int i = 0; i < 8; i++)
#pragma unroll
                for (int j = 0; j < 8; j++)
                    acc[i][j] += af[i] * bw[j];
        }
    }

#pragma unroll
    for (int i = 0; i < 8; i++) {
        int row = by * 128 + ty * 8 + i;
        int col0 = bx * 128 + tx * 8;
        float4 xr0 = *(const float4*)(x + (size_t)row * 1024 + col0);
        float4 xr1 = *(const float4*)(x + (size_t)row * 1024 + col0 + 4);
        float4 bf0 = *(const float4*)(bf + col0);
        float4 bf1 = *(const float4*)(bf + col0 + 4);
        float4 o0, o1;
        o0.x = acc[i][0] + bf0.x + xr0.x; o0.y = acc[i][1] + bf0.y + xr0.y;
        o0.z = acc[i][2] + bf0.z + xr0.z; o0.w = acc[i][3] + bf0.w + xr0.w;
        o1.x = acc[i][4] + bf1.x + xr1.x; o1.y = acc[i][5] + bf1.y + xr1.y;
        o1.z = acc[i][6] + bf1.z + xr1.z; o1.w = acc[i][7] + bf1.w + xr1.w;
        *(float4*)(H + (size_t)row * 1024 + col0)     = o0;
        *(float4*)(H + (size_t)row * 1024 + col0 + 4) = o1;
    }
}

// ============================================================
// Row softmax over N=8192, one CTA per row, values held in regs.
// ============================================================
__device__ __forceinline__ float warpRedMax(float v) {
#pragma unroll
    for (int o = 16; o > 0; o >>= 1) v = fmaxf(v, __shfl_xor_sync(0xffffffffu, v, o));
    return v;
}
__device__ __forceinline__ float warpRedSum(float v) {
#pragma unroll
    for (int o = 16; o > 0; o >>= 1) v += __shfl_xor_sync(0xffffffffu, v, o);
    return v;
}

__global__ __launch_bounds__(256) void softmax_kernel(float* __restrict__ S)
{
    __shared__ float red[8];
    __shared__ float bc;
    float4* row = (float4*)(S + (size_t)blockIdx.x * BANKN);
    const int t = threadIdx.x;

    float4 v[8];
    float mx = -3.4e38f;
#pragma unroll
    for (int i = 0; i < 8; i++) {
        v[i] = row[t + i * 256];
        mx = fmaxf(mx, fmaxf(fmaxf(v[i].x, v[i].y), fmaxf(v[i].z, v[i].w)));
    }
    mx = warpRedMax(mx);
    if ((t & 31) == 0) red[t >> 5] = mx;
    __syncthreads();
    if (t == 0) {
        float m = red[0];
#pragma unroll
        for (int i = 1; i < 8; i++) m = fmaxf(m, red[i]);
        bc = m;
    }
    __syncthreads();
    mx = bc;

    float s = 0.f;
#pragma unroll
    for (int i = 0; i < 8; i++) {
        v[i].x = __expf(v[i].x - mx); v[i].y = __expf(v[i].y - mx);
        v[i].z = __expf(v[i].z - mx); v[i].w = __expf(v[i].w - mx);
        s += v[i].x + v[i].y + v[i].z + v[i].w;
    }
    s = warpRedSum(s);
    __syncthreads();
    if ((t & 31) == 0) red[t >> 5] = s;
    __syncthreads();
    if (t == 0) {
        float tot = 0.f;
#pragma unroll
        for (int i = 0; i < 8; i++) tot += red[i];
        bc = 1.f / tot;
    }
    __syncthreads();
    float inv = bc;
#pragma unroll
    for (int i = 0; i < 8; i++) {
        v[i].x *= inv; v[i].y *= inv; v[i].z *= inv; v[i].w *= inv;
        row[t + i * 256] = v[i];
    }
}

// ============================================================
// LayerNorm over D=1024 per row.
// ============================================================
__global__ __launch_bounds__(256) void ln_kernel(
    const float* __restrict__ H, const float* __restrict__ gamma,
    const float* __restrict__ beta, float* __restrict__ out)
{
    __shared__ float red[8];
    __shared__ float bc;
    const int t = threadIdx.x;
    const float4* row = (const float4*)(H + (size_t)blockIdx.x * DIMN);
    float4 v = row[t];

    float s = v.x + v.y + v.z + v.w;
    s = warpRedSum(s);
    if ((t & 31) == 0) red[t >> 5] = s;
    __syncthreads();
    if (t == 0) {
        float tot = 0.f;
#pragma unroll
        for (int i = 0; i < 8; i++) tot += red[i];
        bc = tot * (1.f / 1024.f);
    }
    __syncthreads();
    float mu = bc;

    float dx = v.x - mu, dy = v.y - mu, dz = v.z - mu, dw = v.w - mu;
    float sq = dx * dx + dy * dy + dz * dz + dw * dw;
    sq = warpRedSum(sq);
    __syncthreads();
    if ((t & 31) == 0) red[t >> 5] = sq;
    __syncthreads();
    if (t == 0) {
        float tot = 0.f;
#pragma unroll
        for (int i = 0; i < 8; i++) tot += red[i];
        bc = rsqrtf(tot * (1.f / 1024.f) + 1e-5f);
    }
    __syncthreads();
    float rs = bc;

    float4 g = ((const float4*)gamma)[t];
    float4 b = ((const float4*)beta)[t];
    float4 o;
    o.x = dx * rs * g.x + b.x;
    o.y = dy * rs * g.y + b.y;
    o.z = dz * rs * g.z + b.z;
    o.w = dw * rs * g.w + b.w;
    ((float4*)(out + (size_t)blockIdx.x * DIMN))[t] = o;
}

// ============================================================
extern "C" void kernel_launch(void* const* d_in, const int* in_sizes, int n_in,
                              void* d_out, int out_size)
{
    const float* x     = (const float*)d_in[0];
    const float* bank  = (const float*)d_in[1];
    const float* wq    = (const float*)d_in[2];
    const float* bq    = (const float*)d_in[3];
    const float* wk    = (const float*)d_in[4];
    const float* bk    = (const float*)d_in[5];
    const float* wv    = (const float*)d_in[6];
    const float* bv    = (const float*)d_in[7];
    const float* wf    = (const float*)d_in[8];
    const float* bf    = (const float*)d_in[9];
    const float* gamma = (const float*)d_in[10];
    const float* beta  = (const float*)d_in[11];
    float* out = (float*)d_out;

    float *Q, *Km, *VT, *S, *R, *H;
    cudaGetSymbolAddress((void**)&Q,  g_Q);
    cudaGetSymbolAddress((void**)&Km, g_K);
    cudaGetSymbolAddress((void**)&VT, g_VT);
    cudaGetSymbolAddress((void**)&S,  g_S);
    cudaGetSymbolAddress((void**)&R,  g_R);
    cudaGetSymbolAddress((void**)&H,  g_H);

    dim3 blk(256);

    // Q = x @ wq^T + bq               [16384,1024]
    gemm_nt_kernel<<<dim3(DIMN / 128, T_TOK / 128), blk>>>(
        x, wq, bq, Q, T_TOK, DIMN, DIMN, 1.f, 0);
    // K = bank @ wk^T + bk            [8192,1024]
    gemm_nt_kernel<<<dim3(DIMN / 128, BANKN / 128), blk>>>(
        bank, wk, bk, Km, BANKN, DIMN, DIMN, 1.f, 0);
    // VT[d][n] = (bank @ wv^T + bv)[n][d]   [1024,8192]
    gemm_nt_kernel<<<dim3(DIMN / 128, BANKN / 128), blk>>>(
        bank, wv, bv, VT, BANKN, DIMN, DIMN, 1.f, 1);
    // S = (Q @ K^T) / 32              [16384,8192]
    gemm_nt_kernel<<<dim3(BANKN / 128, T_TOK / 128), blk>>>(
        Q, Km, nullptr, S, T_TOK, BANKN, DIMN, 0.03125f, 0);
    // softmax rows
    softmax_kernel<<<T_TOK, 256>>>(S);
    // R = attn @ V = attn @ VT^T      [16384,1024]
    gemm_nt_kernel<<<dim3(DIMN / 128, T_TOK / 128), blk>>>(
        S, VT, nullptr, R, T_TOK, DIMN, BANKN, 1.f, 0);
    // H = [x|R] @ wf^T + bf + x       [16384,1024]
    gemm_final_kernel<<<dim3(DIMN / 128, T_TOK / 128), blk>>>(x, R, wf, bf, H);
    // out = LN(H) * gamma + beta
    ln_kernel<<<T_TOK, 256>>>(H, gamma, beta, out);
}

// round 2
// speedup vs baseline: 1.0004x; 1.0004x over previous
#include <cuda_runtime.h>
#include <math.h>

#define T_TOK 16384   // B*S
#define DIMN  1024
#define BANKN 8192

// ---- scratch (allocation-free: device globals) ----
__device__ float g_Q [(size_t)T_TOK * DIMN];   // 64 MB
__device__ float g_K [(size_t)BANKN * DIMN];   // 32 MB
__device__ float g_VT[(size_t)DIMN * BANKN];   // 32 MB (values, transposed: [d][n])
__device__ float g_S [(size_t)T_TOK * BANKN];  // 512 MB (scores -> attn)
__device__ float g_R [(size_t)T_TOK * DIMN];   // 64 MB (retrieved)
__device__ float g_H [(size_t)T_TOK * DIMN];   // 64 MB (pre-LN)

// ============================================================
// Generic NT GEMM: C[M,N] = alpha * A[M,K] * W[N,K]^T (+ bias[N])
// BM=BN=128, BK=8, 256 threads, 8x8 micro-tile per thread.
// transC=1 stores C[col*M + row] (used to produce VT).
// ============================================================
__global__ __launch_bounds__(256) void gemm_nt_kernel(
    const float* __restrict__ A, const float* __restrict__ W,
    const float* __restrict__ bias, float* __restrict__ C,
    int M, int N, int K, float alpha, int transC)
{
    __shared__ float As[8][128];
    __shared__ float Bs[8][128];
    const int tid = threadIdx.x;
    const int tx = tid & 15;        // 16 col-threads
    const int ty = tid >> 4;        // 16 row-threads
    const int bx = blockIdx.x;      // N tile
    const int by = blockIdx.y;      // M tile

    const float* Ab = A + (size_t)by * 128 * K;
    const float* Wb = W + (size_t)bx * 128 * K;
    const int lrow = tid >> 1;          // 0..127
    const int lcol = (tid & 1) * 4;     // 0 or 4

    float acc[8][8];
#pragma unroll
    for (int i = 0; i < 8; i++)
#pragma unroll
        for (int j = 0; j < 8; j++) acc[i][j] = 0.f;

    for (int k0 = 0; k0 < K; k0 += 8) {
        float4 av = *(const float4*)(Ab + (size_t)lrow * K + (k0 + lcol));
        float4 wv = *(const float4*)(Wb + (size_t)lrow * K + (k0 + lcol));
        __syncthreads();
        As[lcol + 0][lrow] = av.x; As[lcol + 1][lrow] = av.y;
        As[lcol + 2][lrow] = av.z; As[lcol + 3][lrow] = av.w;
        Bs[lcol + 0][lrow] = wv.x; Bs[lcol + 1][lrow] = wv.y;
        Bs[lcol + 2][lrow] = wv.z; Bs[lcol + 3][lrow] = wv.w;
        __syncthreads();
#pragma unroll
        for (int kk = 0; kk < 8; kk++) {
            float4 a0 = *(const float4*)&As[kk][ty * 8];
            float4 a1 = *(const float4*)&As[kk][ty * 8 + 4];
            float4 b0 = *(const float4*)&Bs[kk][tx * 8];
            float4 b1 = *(const float4*)&Bs[kk][tx * 8 + 4];
            float af[8] = {a0.x, a0.y, a0.z, a0.w, a1.x, a1.y, a1.z, a1.w};
            float bw[8] = {b0.x, b0.y, b0.z, b0.w, b1.x, b1.y, b1.z, b1.w};
#pragma unroll
            for (int i = 0; i < 8; i++)
#pragma unroll
                for (int j = 0; j < 8; j++)
                    acc[i][j] += af[i] * bw[j];
        }
    }

#pragma unroll
    for (int i = 0; i < 8; i++) {
        int row = by * 128 + ty * 8 + i;
        if (!transC) {
            int col0 = bx * 128 + tx * 8;
            float4 o0, o1;
            float b0 = bias ? bias[col0 + 0] : 0.f;
            float b1 = bias ? bias[col0 + 1] : 0.f;
            float b2 = bias ? bias[col0 + 2] : 0.f;
            float b3 = bias ? bias[col0 + 3] : 0.f;
            float b4 = bias ? bias[col0 + 4] : 0.f;
            float b5 = bias ? bias[col0 + 5] : 0.f;
            float b6 = bias ? bias[col0 + 6] : 0.f;
            float b7 = bias ? bias[col0 + 7] : 0.f;
            o0.x = acc[i][0] * alpha + b0; o0.y = acc[i][1] * alpha + b1;
            o0.z = acc[i][2] * alpha + b2; o0.w = acc[i][3] * alpha + b3;
            o1.x = acc[i][4] * alpha + b4; o1.y = acc[i][5] * alpha + b5;
            o1.z = acc[i][6] * alpha + b6; o1.w = acc[i][7] * alpha + b7;
            *(float4*)(C + (size_t)row * N + col0)     = o0;
            *(float4*)(C + (size_t)row * N + col0 + 4) = o1;
        } else {
#pragma unroll
            for (int j = 0; j < 8; j++) {
                int col = bx * 128 + tx * 8 + j;
                float v = acc[i][j] * alpha + (bias ? bias[col] : 0.f);
                C[(size_t)col * M + row] = v;
            }
        }
    }
}

// ============================================================
// Final GEMM: H[t,d] = sum_k [x|R][t,k] * wf[d,k] + bf[d] + x[t,d]
// M = T_TOK, N = DIMN, K = 2048 (first 1024 from x, rest from R)
// ============================================================
__global__ __launch_bounds__(256) void gemm_final_kernel(
    const float* __restrict__ x, const float* __restrict__ R,
    const float* __restrict__ wf, const float* __restrict__ bf,
    float* __restrict__ H)
{
    __shared__ float As[8][128];
    __shared__ float Bs[8][128];
    const int tid = threadIdx.x;
    const int tx = tid & 15;
    const int ty = tid >> 4;
    const int bx = blockIdx.x;
    const int by = blockIdx.y;
    const int lrow = tid >> 1;
    const int lcol = (tid & 1) * 4;

    const float* Wb = wf + (size_t)bx * 128 * 2048;

    float acc[8][8];
#pragma unroll
    for (int i = 0; i < 8; i++)
#pragma unroll
        for (int j = 0; j < 8; j++) acc[i][j] = 0.f;

    for (int k0 = 0; k0 < 2048; k0 += 8) {
        const float* Ab = (k0 < 1024)
            ? (x + (size_t)by * 128 * 1024 + k0)
            : (R + (size_t)by * 128 * 1024 + (k0 - 1024));
        float4 av = *(const float4*)(Ab + (size_t)lrow * 1024 + lcol);
        float4 wv = *(const float4*)(Wb + (size_t)lrow * 2048 + k0 + lcol);
        __syncthreads();
        As[lcol + 0][lrow] = av.x; As[lcol + 1][lrow] = av.y;
        As[lcol + 2][lrow] = av.z; As[lcol + 3][lrow] = av.w;
        Bs[lcol + 0][lrow] = wv.x; Bs[lcol + 1][lrow] = wv.y;
        Bs[lcol + 2][lrow] = wv.z; Bs[lcol + 3][lrow] = wv.w;
        __syncthreads();
#pragma unroll
        for (int kk = 0; kk < 8; kk++) {
            float4 a0 = *(const float4*)&As[kk][ty * 8];
            float4 a1 = *(const float4*)&As[kk][ty * 8 + 4];
            float4 b0 = *(const float4*)&Bs[kk][tx * 8];
            float4 b1 = *(const float4*)&Bs[kk][tx * 8 + 4];
            float af[8] = {a0.x, a0.y, a0.z, a0.w, a1.x, a1.y, a1.z, a1.w};
            float bw[8] = {b0.x, b0.y, b0.z, b0.w, b1.x, b1.y, b1.z, b1.w};
#pragma unroll
            for (int i = 0; i < 8; i++)
#pragma unroll
                for (int j = 0; j < 8; j++)
                    acc[i][j] += af[i] * bw[j];
        }
    }

#pragma unroll
    for (int i = 0; i < 8; i++) {
        int row = by * 128 + ty * 8 + i;
        int col0 = bx * 128 + tx * 8;
        float4 xr0 = *(const float4*)(x + (size_t)row * 1024 + col0);
        float4 xr1 = *(const float4*)(x + (size_t)row * 1024 + col0 + 4);
        float4 bf0 = *(const float4*)(bf + col0);
        float4 bf1 = *(const float4*)(bf + col0 + 4);
        float4 o0, o1;
        o0.x = acc[i][0] + bf0.x + xr0.x; o0.y = acc[i][1] + bf0.y + xr0.y;
        o0.z = acc[i][2] + bf0.z + xr0.z; o0.w = acc[i][3] + bf0.w + xr0.w;
        o1.x = acc[i][4] + bf1.x + xr1.x; o1.y = acc[i][5] + bf1.y + xr1.y;
        o1.z = acc[i][6] + bf1.z + xr1.z; o1.w = acc[i][7] + bf1.w + xr1.w;
        *(float4*)(H + (size_t)row * 1024 + col0)     = o0;
        *(float4*)(H + (size_t)row * 1024 + col0 + 4) = o1;
    }
}

// ============================================================
// Row softmax over N=8192, one CTA per row, values held in regs.
// ============================================================
__device__ __forceinline__ float warpRedMax(float v) {
#pragma unroll
    for (int o = 16; o > 0; o >>= 1) v = fmaxf(v, __shfl_xor_sync(0xffffffffu, v, o));
    return v;
}
__device__ __forceinline__ float warpRedSum(float v) {
#pragma unroll
    for (int o = 16; o > 0; o >>= 1) v += __shfl_xor_sync(0xffffffffu, v, o);
    return v;
}

__global__ __launch_bounds__(256) void softmax_kernel(float* __restrict__ S)
{
    __shared__ float red[8];
    __shared__ float bc;
    float4* row = (float4*)(S + (size_t)blockIdx.x * BANKN);
    const int t = threadIdx.x;

    float4 v[8];
    float mx = -3.4e38f;
#pragma unroll
    for (int i = 0; i < 8; i++) {
        v[i] = row[t + i * 256];
        mx = fmaxf(mx, fmaxf(fmaxf(v[i].x, v[i].y), fmaxf(v[i].z, v[i].w)));
    }
    mx = warpRedMax(mx);
    if ((t & 31) == 0) red[t >> 5] = mx;
    __syncthreads();
    if (t == 0) {
        float m = red[0];
#pragma unroll
        for (int i = 1; i < 8; i++) m = fmaxf(m, red[i]);
        bc = m;
    }
    __syncthreads();
    mx = bc;

    float s = 0.f;
#pragma unroll
    for (int i = 0; i < 8; i++) {
        v[i].x = __expf(v[i].x - mx); v[i].y = __expf(v[i].y - mx);
        v[i].z = __expf(v[i].z - mx); v[i].w = __expf(v[i].w - mx);
        s += v[i].x + v[i].y + v[i].z + v[i].w;
    }
    s = warpRedSum(s);
    __syncthreads();
    if ((t & 31) == 0) red[t >> 5] = s;
    __syncthreads();
    if (t == 0) {
        float tot = 0.f;
#pragma unroll
        for (int i = 0; i < 8; i++) tot += red[i];
        bc = 1.f / tot;
    }
    __syncthreads();
    float inv = bc;
#pragma unroll
    for (int i = 0; i < 8; i++) {
        v[i].x *= inv; v[i].y *= inv; v[i].z *= inv; v[i].w *= inv;
        row[t + i * 256] = v[i];
    }
}

// ============================================================
// LayerNorm over D=1024 per row.
// ============================================================
__global__ __launch_bounds__(256) void ln_kernel(
    const float* __restrict__ H, const float* __restrict__ gamma,
    const float* __restrict__ beta, float* __restrict__ out)
{
    __shared__ float red[8];
    __shared__ float bc;
    const int t = threadIdx.x;
    const float4* row = (const float4*)(H + (size_t)blockIdx.x * DIMN);
    float4 v = row[t];

    float s = v.x + v.y + v.z + v.w;
    s = warpRedSum(s);
    if ((t & 31) == 0) red[t >> 5] = s;
    __syncthreads();
    if (t == 0) {
        float tot = 0.f;
#pragma unroll
        for (int i = 0; i < 8; i++) tot += red[i];
        bc = tot * (1.f / 1024.f);
    }
    __syncthreads();
    float mu = bc;

    float dx = v.x - mu, dy = v.y - mu, dz = v.z - mu, dw = v.w - mu;
    float sq = dx * dx + dy * dy + dz * dz + dw * dw;
    sq = warpRedSum(sq);
    __syncthreads();
    if ((t & 31) == 0) red[t >> 5] = sq;
    __syncthreads();
    if (t == 0) {
        float tot = 0.f;
#pragma unroll
        for (int i = 0; i < 8; i++) tot += red[i];
        bc = rsqrtf(tot * (1.f / 1024.f) + 1e-5f);
    }
    __syncthreads();
    float rs = bc;

    float4 g = ((const float4*)gamma)[t];
    float4 b = ((const float4*)beta)[t];
    float4 o;
    o.x = dx * rs * g.x + b.x;
    o.y = dy * rs * g.y + b.y;
    o.z = dz * rs * g.z + b.z;
    o.w = dw * rs * g.w + b.w;
    ((float4*)(out + (size_t)blockIdx.x * DIMN))[t] = o;
}

// ============================================================
extern "C" void kernel_launch(void* const* d_in, const int* in_sizes, int n_in,
                              void* d_out, int out_size)
{
    const float* x     = (const float*)d_in[0];
    const float* bank  = (const float*)d_in[1];
    const float* wq    = (const float*)d_in[2];
    const float* bq    = (const float*)d_in[3];
    const float* wk    = (const float*)d_in[4];
    const float* bk    = (const float*)d_in[5];
    const float* wv    = (const float*)d_in[6];
    const float* bv    = (const float*)d_in[7];
    const float* wf    = (const float*)d_in[8];
    const float* bf    = (const float*)d_in[9];
    const float* gamma = (const float*)d_in[10];
    const float* beta  = (const float*)d_in[11];
    float* out = (float*)d_out;

    float *Q, *Km, *VT, *S, *R, *H;
    cudaGetSymbolAddress((void**)&Q,  g_Q);
    cudaGetSymbolAddress((void**)&Km, g_K);
    cudaGetSymbolAddress((void**)&VT, g_VT);
    cudaGetSymbolAddress((void**)&S,  g_S);
    cudaGetSymbolAddress((void**)&R,  g_R);
    cudaGetSymbolAddress((void**)&H,  g_H);

    dim3 blk(256);

    // Q = x @ wq^T + bq               [16384,1024]
    gemm_nt_kernel<<<dim3(DIMN / 128, T_TOK / 128), blk>>>(
        x, wq, bq, Q, T_TOK, DIMN, DIMN, 1.f, 0);
    // K = bank @ wk^T + bk            [8192,1024]
    gemm_nt_kernel<<<dim3(DIMN / 128, BANKN / 128), blk>>>(
        bank, wk, bk, Km, BANKN, DIMN, DIMN, 1.f, 0);
    // VT[d][n] = (bank @ wv^T + bv)[n][d]   [1024,8192]
    gemm_nt_kernel<<<dim3(DIMN / 128, BANKN / 128), blk>>>(
        bank, wv, bv, VT, BANKN, DIMN, DIMN, 1.f, 1);
    // S = (Q @ K^T) / 32              [16384,8192]
    gemm_nt_kernel<<<dim3(BANKN / 128, T_TOK / 128), blk>>>(
        Q, Km, nullptr, S, T_TOK, BANKN, DIMN, 0.03125f, 0);
    // softmax rows
    softmax_kernel<<<T_TOK, 256>>>(S);
    // R = attn @ V = attn @ VT^T      [16384,1024]
    gemm_nt_kernel<<<dim3(DIMN / 128, T_TOK / 128), blk>>>(
        S, VT, nullptr, R, T_TOK, DIMN, BANKN, 1.f, 0);
    // H = [x|R] @ wf^T + bf + x       [16384,1024]
    gemm_final_kernel<<<dim3(DIMN / 128, T_TOK / 128), blk>>>(x, R, wf, bf, H);
    // out = LN(H) * gamma + beta
    ln_kernel<<<T_TOK, 256>>>(H, gamma, beta, out);
}